// round 1
// baseline (speedup 1.0000x reference)
#include <cuda_runtime.h>
#include <math.h>

#define Bdim 8
#define Cdim 32
#define Hdim 128
#define Wdim 128
#define OUTdim 32
#define HW (Hdim*Wdim)            /* 16384 */
#define NPIX (Bdim*HW)            /* 131072 */
#define NBLK_A 512

// ---- scratch (static device globals; no runtime allocation) ----
__device__ float g_conv[4*NPIX];      // raw conv+bias outputs: v0,v1,z0,z1 planes
__device__ float g_partial[NBLK_A*8]; // per-block partial sums (4 sums + 4 sumsq)
__device__ float g_stats[12];         // mean[4], scale[4]=gamma*rsqrt(var+eps), shift[4]=beta

// =====================================================================
// Kernel A: 7-tap vert/horz convs (zero pad) + bias; per-block reduction
// =====================================================================
__global__ __launch_bounds__(256) void convbn_kernel(
    const float* __restrict__ x,
    const float* __restrict__ w_vrt, const float* __restrict__ b_vrt,
    const float* __restrict__ w_hrz, const float* __restrict__ b_hrz)
{
    __shared__ float swv[448], swh[448];   // [2][32][7]
    __shared__ float red[8][8];
    int tid = threadIdx.x;
    for (int i = tid; i < 448; i += 256) { swv[i] = w_vrt[i]; swh[i] = w_hrz[i]; }
    __syncthreads();

    int pix = blockIdx.x*256 + tid;
    int b = pix >> 14; int rem = pix & (HW-1); int h = rem >> 7; int w = rem & 127;
    const float* Xb = x + (size_t)b*Cdim*HW;

    float v0=0.f, v1=0.f, z0=0.f, z1=0.f;
    for (int c = 0; c < Cdim; ++c) {
        const float* Xc = Xb + c*HW;
        #pragma unroll
        for (int t = 0; t < 7; ++t) {
            int hh = h + t - 3;
            float xv = (hh >= 0 && hh < Hdim) ? Xc[hh*Wdim + w] : 0.f;
            v0 = fmaf(xv, swv[c*7+t],       v0);
            v1 = fmaf(xv, swv[224 + c*7+t], v1);
            int ww = w + t - 3;
            float xh = (ww >= 0 && ww < Wdim) ? Xc[h*Wdim + ww] : 0.f;
            z0 = fmaf(xh, swh[c*7+t],       z0);
            z1 = fmaf(xh, swh[224 + c*7+t], z1);
        }
    }
    v0 += b_vrt[0]; v1 += b_vrt[1]; z0 += b_hrz[0]; z1 += b_hrz[1];

    g_conv[          pix] = v0;
    g_conv[  NPIX +  pix] = v1;
    g_conv[2*NPIX +  pix] = z0;
    g_conv[3*NPIX +  pix] = z1;

    float vals[8] = {v0, v1, z0, z1, v0*v0, v1*v1, z0*z0, z1*z1};
    #pragma unroll
    for (int k = 0; k < 8; ++k) {
        float s = vals[k];
        #pragma unroll
        for (int off = 16; off; off >>= 1) s += __shfl_down_sync(0xffffffffu, s, off);
        if ((tid & 31) == 0) red[tid>>5][k] = s;
    }
    __syncthreads();
    if (tid < 8) {
        float s = 0.f;
        #pragma unroll
        for (int wr = 0; wr < 8; ++wr) s += red[wr][tid];
        g_partial[blockIdx.x*8 + tid] = s;
    }
}

// =====================================================================
// Kernel B: finalize BN stats (deterministic)
// =====================================================================
__global__ void stats_kernel(
    const float* __restrict__ g_vrt, const float* __restrict__ be_vrt,
    const float* __restrict__ g_hrz, const float* __restrict__ be_hrz)
{
    __shared__ float sh[8];
    int k = threadIdx.x;
    if (k < 8) {
        float s = 0.f;
        for (int i = 0; i < NBLK_A; ++i) s += g_partial[i*8 + k];
        sh[k] = s;
    }
    __syncwarp();
    if (k < 4) {
        const float inv = 1.f / (float)NPIX;
        float mean = sh[k] * inv;
        float var  = sh[k+4] * inv - mean*mean;
        float gamma = (k < 2) ? g_vrt[k] : g_hrz[k-2];
        float beta  = (k < 2) ? be_vrt[k] : be_hrz[k-2];
        g_stats[k]     = mean;
        g_stats[4 + k] = gamma * rsqrtf(var + 1e-5f);
        g_stats[8 + k] = beta;
    }
}

// =====================================================================
// Kernel C: per-pixel deformable sampling + 32x512 matvec
// =====================================================================
__global__ __launch_bounds__(256, 2) void main_kernel(
    const float* __restrict__ x, const float* __restrict__ w_pk,
    const float* __restrict__ b_pk, float* __restrict__ out)
{
    extern __shared__ float sw[];          // w_pk [32][32][16] = 16384 floats, + bias 32
    float* sb = sw + 16384;
    int tid = threadIdx.x;
    {
        const float4* src = (const float4*)w_pk;
        float4* dst = (float4*)sw;
        #pragma unroll
        for (int i = 0; i < 16; ++i) dst[tid + i*256] = src[tid + i*256];
        if (tid < 32) sb[tid] = b_pk[tid];
    }
    __syncthreads();

    int pix = blockIdx.x*256 + tid;
    int b = pix >> 14; int rem = pix & (HW-1); int h = rem >> 7; int w = rem & 127;

    // gb0..gb3 = 2*sigmoid(BN(conv))
    float gb[4];
    #pragma unroll
    for (int j = 0; j < 4; ++j) {
        float cv = g_conv[j*NPIX + pix];
        float t = (cv - g_stats[j]) * g_stats[4+j] + g_stats[8+j];
        gb[j] = 2.f / (1.f + expf(-t));
    }

    int rm[5], cm[5];
    #pragma unroll
    for (int i = 0; i < 5; ++i) {
        rm[i] = min(max(h + i - 2, 0), 127);
        cm[i] = min(max(w + i - 2, 0), 127);
    }

    int off[16];
    float a[4];
    float eBw, eLw; int eBoff, eLoff;
    {
        float u, q, qlc, qrc, uc;
        // --- Top block (n=0..3): p_x = h - gb0 (frac), p_y = w+n (int, never rb-weighted)
        u = (float)h - gb[0];
        q = floorf(u);
        qlc = fminf(fmaxf(q, 0.f), 131.f);
        uc  = fminf(fmaxf(u, 0.f), 131.f);
        a[0] = 1.f + qlc - uc;
        int rT = min(max((int)qlc - 2, 0), 127);
        off[0]=rT*Wdim+cm[0]; off[1]=rT*Wdim+cm[1]; off[2]=rT*Wdim+cm[2]; off[3]=rT*Wdim+cm[3];
        // --- Right block (n=4..7): p_y = w+4+gb3 (frac), p_x = h+(n-4) (int)
        u = (float)w + 4.f + gb[3];
        q = floorf(u);
        qlc = fminf(fmaxf(q, 0.f), 131.f);
        uc  = fminf(fmaxf(u, 0.f), 131.f);
        a[1] = 1.f + qlc - uc;
        int cR = min(max((int)qlc - 2, 0), 127);
        off[4]=rm[0]*Wdim+cR; off[5]=rm[1]*Wdim+cR; off[6]=rm[2]*Wdim+cR; off[7]=rm[3]*Wdim+cR;
        // --- Bottom block (n=8..11): p_x = h+4+gb1 (frac), p_y = w+(n-7) (int; clips at 131)
        u = (float)h + 4.f + gb[1];
        q = floorf(u);
        qlc = fminf(fmaxf(q, 0.f), 131.f);
        qrc = fminf(fmaxf(q + 1.f, 0.f), 131.f);
        uc  = fminf(fmaxf(u, 0.f), 131.f);
        a[2] = 1.f + qlc - uc;
        float aBr = 1.f - (qrc - uc);
        int rB  = min(max((int)qlc - 2, 0), 127);
        int rBr = min(max((int)qrc - 2, 0), 127);
        off[8]=rB*Wdim+cm[1]; off[9]=rB*Wdim+cm[2]; off[10]=rB*Wdim+cm[3]; off[11]=rB*Wdim+cm[4];
        eBw  = (w == 127) ? aBr : 0.f;   // rb corner only live when p_y hits 131 (n=11,w=127)
        eBoff = rBr*Wdim + 127;
        // --- Left block (n=12..15): p_y = w - gb2 (frac), p_x = h+(n-11) (int; clips at 131)
        u = (float)w - gb[2];
        q = floorf(u);
        qlc = fminf(fmaxf(q, 0.f), 131.f);
        qrc = fminf(fmaxf(q + 1.f, 0.f), 131.f);
        uc  = fminf(fmaxf(u, 0.f), 131.f);
        a[3] = 1.f + qlc - uc;
        float aLr = 1.f - (qrc - uc);
        int cL  = min(max((int)qlc - 2, 0), 127);
        int cLr = min(max((int)qrc - 2, 0), 127);
        off[12]=rm[1]*Wdim+cL; off[13]=rm[2]*Wdim+cL; off[14]=rm[3]*Wdim+cL; off[15]=rm[4]*Wdim+cL;
        eLw  = (h == 127) ? aLr : 0.f;   // rb corner only live when p_x hits 131 (n=15,h=127)
        eLoff = 127*Wdim + cLr;
    }

    float acc[32];
    #pragma unroll
    for (int o = 0; o < 32; ++o) acc[o] = 0.f;

    const float* Xb = x + (size_t)b*Cdim*HW;
    int ctr = h*Wdim + w;

    for (int c = 0; c < Cdim; ++c) {
        const float* Xc = Xb + c*HW;
        float xc = Xc[ctr];
        float d[16];
        #pragma unroll
        for (int n = 0; n < 16; ++n)
            d[n] = fmaf(-a[n>>2], Xc[off[n]], xc);
        d[11] = fmaf(-eBw, Xc[eBoff], d[11]);
        d[15] = fmaf(-eLw, Xc[eLoff], d[15]);

        const float4* wc = ((const float4*)sw) + c*4;   // element (o,c,n): o*128 + c*4 float4s
        #pragma unroll
        for (int o = 0; o < 32; ++o) {
            const float4* wp = wc + o*128;
            float4 w0 = wp[0], w1 = wp[1], w2 = wp[2], w3 = wp[3];
            float s = acc[o];
            s = fmaf(w0.x, d[0],  s); s = fmaf(w0.y, d[1],  s);
            s = fmaf(w0.z, d[2],  s); s = fmaf(w0.w, d[3],  s);
            s = fmaf(w1.x, d[4],  s); s = fmaf(w1.y, d[5],  s);
            s = fmaf(w1.z, d[6],  s); s = fmaf(w1.w, d[7],  s);
            s = fmaf(w2.x, d[8],  s); s = fmaf(w2.y, d[9],  s);
            s = fmaf(w2.z, d[10], s); s = fmaf(w2.w, d[11], s);
            s = fmaf(w3.x, d[12], s); s = fmaf(w3.y, d[13], s);
            s = fmaf(w3.z, d[14], s); s = fmaf(w3.w, d[15], s);
            acc[o] = s;
        }
    }

    int obase = (b*OUTdim)*HW + ctr;
    #pragma unroll
    for (int o = 0; o < 32; ++o)
        out[obase + o*HW] = acc[o] + sb[o];
}

// =====================================================================
extern "C" void kernel_launch(void* const* d_in, const int* in_sizes, int n_in,
                              void* d_out, int out_size)
{
    const float* x      = (const float*)d_in[0];
    const float* w_vrt  = (const float*)d_in[1];
    const float* b_vrt  = (const float*)d_in[2];
    const float* g_vrt  = (const float*)d_in[3];
    const float* be_vrt = (const float*)d_in[4];
    const float* w_hrz  = (const float*)d_in[5];
    const float* b_hrz  = (const float*)d_in[6];
    const float* g_hrz  = (const float*)d_in[7];
    const float* be_hrz = (const float*)d_in[8];
    const float* w_pk   = (const float*)d_in[9];
    const float* b_pk   = (const float*)d_in[10];
    float* out = (float*)d_out;

    convbn_kernel<<<NBLK_A, 256>>>(x, w_vrt, b_vrt, w_hrz, b_hrz);
    stats_kernel<<<1, 32>>>(g_vrt, be_vrt, g_hrz, be_hrz);

    const int smem = (16384 + 32) * sizeof(float);
    cudaFuncSetAttribute(main_kernel, cudaFuncAttributeMaxDynamicSharedMemorySize, smem);
    main_kernel<<<NPIX/256, 256, smem>>>(x, w_pk, b_pk, out);
}